// round 1
// baseline (speedup 1.0000x reference)
#include <cuda_runtime.h>
#include <cstdint>

#define BN_EPS 1e-5f

// ---------------- scratch (no allocations allowed) ----------------
__device__ float g_x1[200000 * 64];        // conv1 output (N x 64), ~51 MB
__device__ float g_x2[(32768 + 1) * 128];  // conv2 output (M x 128)
__device__ float g_stats[512];             // [sum | sumsq | a | d] per channel

// ---------------- packed f32x2 helpers ----------------
static __device__ __forceinline__ unsigned long long pack2(float x) {
    unsigned long long r;
    asm("mov.b64 %0, {%1, %1};" : "=l"(r) : "f"(x));
    return r;
}
static __device__ __forceinline__ void fma2(unsigned long long& acc,
                                            unsigned long long a,
                                            unsigned long long b) {
    asm("fma.rn.f32x2 %0, %1, %2, %0;" : "+l"(acc) : "l"(a), "l"(b));
}
static __device__ __forceinline__ float lo32(unsigned long long v) {
    return __uint_as_float((unsigned)v);
}
static __device__ __forceinline__ float hi32(unsigned long long v) {
    return __uint_as_float((unsigned)(v >> 32));
}

static __device__ __forceinline__ void red_add4(float* p, float a, float b, float c, float d) {
    asm volatile("red.global.add.v4.f32 [%0], {%1, %2, %3, %4};"
                 :: "l"(p), "f"(a), "f"(b), "f"(c), "f"(d) : "memory");
}
static __device__ __forceinline__ void red_add2(float* p, float a, float b) {
    asm volatile("red.global.add.v2.f32 [%0], {%1, %2};"
                 :: "l"(p), "f"(a), "f"(b) : "memory");
}

// ---------------- sparse conv: gather -> GEMM -> scatter-add ----------------
// Grid: (NBX, 27). Block: 128 threads. Each block owns offset k = blockIdx.y,
// keeps W_k fully in SMEM, loops over 64-pair tiles.
// Pad pairs have rin == n_in (trailing); they load zeros and skip scatter.
template <int CIN, int COUT>
__global__ __launch_bounds__(128)
void conv_scatter(const float* __restrict__ fin, const float* __restrict__ W,
                  const int* __restrict__ rin, const int* __restrict__ rout,
                  float* __restrict__ out, int P, int n_in) {
    constexpr int NCPT = COUT / 32;   // couts per thread (2 or 4)
    constexpr int ASTR = 68;          // A-tile stride (pairs dim), 16B-friendly

    extern __shared__ float sm[];
    float* Ws = sm;                   // CIN*COUT
    float* As = sm + CIN * COUT;      // CIN * ASTR (transposed A tile)
    __shared__ int s_in[64];
    __shared__ int s_out[64];

    const int tid = threadIdx.x;
    const int k = blockIdx.y;

    // cache W_k in SMEM
    {
        const float4* wg = reinterpret_cast<const float4*>(W + (size_t)k * CIN * COUT);
        float4* ws4 = reinterpret_cast<float4*>(Ws);
        for (int i = tid; i < CIN * COUT / 4; i += 128) ws4[i] = wg[i];
    }

    const int lane = tid & 31;
    const int wid = tid >> 5;
    const int p0 = wid * 16;          // each warp: 16 pairs
    const int rbase = k * P;
    const int ntiles = (P + 63) >> 6;

    for (int t = blockIdx.x; t < ntiles; t += gridDim.x) {
        const int base = t << 6;
        if (tid < 64) {
            int idx = base + tid;
            s_in[tid]  = (idx < P) ? rin[rbase + idx]  : n_in;
            s_out[tid] = (idx < P) ? rout[rbase + idx] : 0;
        }
        __syncthreads();

        if (s_in[0] != n_in) {  // tile has at least one real pair (pads trail)
            // gather A tile, transposed: As[cin][pair]
#pragma unroll
            for (int h = 0; h < 2; h++) {
                int p = (tid >> 2) + h * 32;
                int row = s_in[p];
                bool v = (row != n_in);
                const float4* frow = reinterpret_cast<const float4*>(fin + (size_t)row * CIN);
#pragma unroll
                for (int j = 0; j < CIN / 16; j++) {
                    int c4 = (tid & 3) + j * 4;
                    float4 val = v ? frow[c4] : make_float4(0.f, 0.f, 0.f, 0.f);
                    As[(c4 * 4 + 0) * ASTR + p] = val.x;
                    As[(c4 * 4 + 1) * ASTR + p] = val.y;
                    As[(c4 * 4 + 2) * ASTR + p] = val.z;
                    As[(c4 * 4 + 3) * ASTR + p] = val.w;
                }
            }
            __syncthreads();

            unsigned long long acc[8][NCPT];
#pragma unroll
            for (int i = 0; i < 8; i++)
#pragma unroll
                for (int c = 0; c < NCPT; c++) acc[i][c] = 0ull;

#pragma unroll 4
            for (int cin = 0; cin < CIN; cin++) {
                const float* ar = As + cin * ASTR + p0;
                ulonglong2 a01 = *reinterpret_cast<const ulonglong2*>(ar);
                ulonglong2 a23 = *reinterpret_cast<const ulonglong2*>(ar + 4);
                ulonglong2 a45 = *reinterpret_cast<const ulonglong2*>(ar + 8);
                ulonglong2 a67 = *reinterpret_cast<const ulonglong2*>(ar + 12);
                unsigned long long av[8] = {a01.x, a01.y, a23.x, a23.y,
                                            a45.x, a45.y, a67.x, a67.y};
                unsigned long long wp[NCPT];
                if constexpr (NCPT == 4) {
                    float4 wv = *reinterpret_cast<const float4*>(Ws + cin * COUT + lane * 4);
                    wp[0] = pack2(wv.x); wp[1] = pack2(wv.y);
                    wp[2] = pack2(wv.z); wp[3] = pack2(wv.w);
                } else {
                    float2 wv = *reinterpret_cast<const float2*>(Ws + cin * COUT + lane * 2);
                    wp[0] = pack2(wv.x); wp[1] = pack2(wv.y);
                }
#pragma unroll
                for (int i = 0; i < 8; i++)
#pragma unroll
                    for (int c = 0; c < NCPT; c++) fma2(acc[i][c], av[i], wp[c]);
            }

            // scatter-add (outputs distinct within an offset; atomics for cross-offset)
#pragma unroll
            for (int i = 0; i < 8; i++) {
                int p = p0 + 2 * i;
                if (s_in[p] != n_in) {
                    float* dst = out + (size_t)s_out[p] * COUT + lane * NCPT;
                    if constexpr (NCPT == 4)
                        red_add4(dst, lo32(acc[i][0]), lo32(acc[i][1]),
                                      lo32(acc[i][2]), lo32(acc[i][3]));
                    else
                        red_add2(dst, lo32(acc[i][0]), lo32(acc[i][1]));
                }
                if (s_in[p + 1] != n_in) {
                    float* dst = out + (size_t)s_out[p + 1] * COUT + lane * NCPT;
                    if constexpr (NCPT == 4)
                        red_add4(dst, hi32(acc[i][0]), hi32(acc[i][1]),
                                      hi32(acc[i][2]), hi32(acc[i][3]));
                    else
                        red_add2(dst, hi32(acc[i][0]), hi32(acc[i][1]));
                }
            }
        }
        __syncthreads();
    }
}

// ---------------- BatchNorm (training stats) + ReLU ----------------
template <int COUT>
__global__ void bn_stats(const float* __restrict__ x, int R, float* __restrict__ st) {
    constexpr int RPB = 256 / COUT;
    int tid = threadIdx.x;
    int c = tid & (COUT - 1);
    int r = blockIdx.x * RPB + tid / COUT;
    int stride = gridDim.x * RPB;
    float s = 0.f, sq = 0.f;
    for (; r < R; r += stride) {
        float v = x[(size_t)r * COUT + c];
        s += v;
        sq += v * v;
    }
    atomicAdd(&st[c], s);
    atomicAdd(&st[COUT + c], sq);
}

template <int COUT>
__global__ void bn_finalize(const float* __restrict__ g, const float* __restrict__ b,
                            float invR, float* __restrict__ st) {
    int c = threadIdx.x;
    if (c < COUT) {
        float mu = st[c] * invR;
        float var = st[COUT + c] * invR - mu * mu;
        float a = rsqrtf(var + BN_EPS) * g[c];
        st[2 * COUT + c] = a;
        st[3 * COUT + c] = b[c] - mu * a;
    }
}

template <int COUT>
__global__ void bn_apply_relu(float* __restrict__ x, int total4,
                              const float* __restrict__ st) {
    int i = blockIdx.x * blockDim.x + threadIdx.x;
    if (i >= total4) return;
    float4 v = reinterpret_cast<float4*>(x)[i];
    int c0 = (i * 4) & (COUT - 1);
    const float* A = st + 2 * COUT;
    const float* D = st + 3 * COUT;
    v.x = fmaxf(fmaf(v.x, A[c0 + 0], D[c0 + 0]), 0.f);
    v.y = fmaxf(fmaf(v.y, A[c0 + 1], D[c0 + 1]), 0.f);
    v.z = fmaxf(fmaf(v.z, A[c0 + 2], D[c0 + 2]), 0.f);
    v.w = fmaxf(fmaf(v.w, A[c0 + 3], D[c0 + 3]), 0.f);
    reinterpret_cast<float4*>(x)[i] = v;
}

// ---------------- launch ----------------
extern "C" void kernel_launch(void* const* d_in, const int* in_sizes, int n_in,
                              void* d_out, int out_size) {
    const float* feats = (const float*)d_in[0];
    const float* W1 = (const float*)d_in[1];
    const float* W2 = (const float*)d_in[2];
    const float* W3 = (const float*)d_in[3];
    const float* g1 = (const float*)d_in[4];
    const float* b1 = (const float*)d_in[5];
    const float* g2 = (const float*)d_in[6];
    const float* b2 = (const float*)d_in[7];
    const float* g3 = (const float*)d_in[8];
    const float* b3 = (const float*)d_in[9];
    const int* rb1i = (const int*)d_in[10];
    const int* rb1o = (const int*)d_in[11];
    const int* rb2i = (const int*)d_in[12];
    const int* rb2o = (const int*)d_in[13];
    const int* rb3i = (const int*)d_in[14];
    const int* rb3o = (const int*)d_in[15];

    const int N = in_sizes[0] / 64;
    const int M = out_size / 128;
    const int P1 = in_sizes[10] / 27;
    const int P2 = in_sizes[12] / 27;
    const int P3 = in_sizes[14] / 27;

    float *x1, *x2, *st;
    cudaGetSymbolAddress((void**)&x1, g_x1);
    cudaGetSymbolAddress((void**)&x2, g_x2);
    cudaGetSymbolAddress((void**)&st, g_stats);
    float* out = (float*)d_out;

    const int smem1 = (64 * 64 + 64 * 68) * 4;
    const int smem2 = (64 * 128 + 64 * 68) * 4;
    const int smem3 = (128 * 128 + 128 * 68) * 4;
    cudaFuncSetAttribute(conv_scatter<64, 64>,  cudaFuncAttributeMaxDynamicSharedMemorySize, smem1);
    cudaFuncSetAttribute(conv_scatter<64, 128>, cudaFuncAttributeMaxDynamicSharedMemorySize, smem2);
    cudaFuncSetAttribute(conv_scatter<128, 128>, cudaFuncAttributeMaxDynamicSharedMemorySize, smem3);

    dim3 cgrid(128, 27);

    // ---- stage 1: submanifold conv (N x 64) ----
    cudaMemsetAsync(x1, 0, (size_t)N * 64 * sizeof(float), 0);
    conv_scatter<64, 64><<<cgrid, 128, smem1, 0>>>(feats, W1, rb1i, rb1o, x1, P1, N);
    cudaMemsetAsync(st, 0, 512 * sizeof(float), 0);
    bn_stats<64><<<512, 256, 0, 0>>>(x1, N, st);
    bn_finalize<64><<<1, 64, 0, 0>>>(g1, b1, 1.f / (float)N, st);
    {
        int tot4 = N * 64 / 4;
        bn_apply_relu<64><<<(tot4 + 255) / 256, 256, 0, 0>>>(x1, tot4, st);
    }

    // ---- stage 2: stride-2 conv (M x 128) ----
    cudaMemsetAsync(x2, 0, (size_t)M * 128 * sizeof(float), 0);
    conv_scatter<64, 128><<<cgrid, 128, smem2, 0>>>(x1, W2, rb2i, rb2o, x2, P2, N);
    cudaMemsetAsync(st, 0, 512 * sizeof(float), 0);
    bn_stats<128><<<512, 256, 0, 0>>>(x2, M, st);
    bn_finalize<128><<<1, 128, 0, 0>>>(g2, b2, 1.f / (float)M, st);
    {
        int tot4 = M * 128 / 4;
        bn_apply_relu<128><<<(tot4 + 255) / 256, 256, 0, 0>>>(x2, tot4, st);
    }

    // ---- stage 3: submanifold conv on 32^3 grid (M x 128) -> d_out ----
    cudaMemsetAsync(out, 0, (size_t)M * 128 * sizeof(float), 0);
    conv_scatter<128, 128><<<cgrid, 128, smem3, 0>>>(x2, W3, rb3i, rb3o, out, P3, M);
    cudaMemsetAsync(st, 0, 512 * sizeof(float), 0);
    bn_stats<128><<<512, 256, 0, 0>>>(out, M, st);
    bn_finalize<128><<<1, 128, 0, 0>>>(g3, b3, 1.f / (float)M, st);
    {
        int tot4 = M * 128 / 4;
        bn_apply_relu<128><<<(tot4 + 255) / 256, 256, 0, 0>>>(out, tot4, st);
    }
}